// round 5
// baseline (speedup 1.0000x reference)
#include <cuda_runtime.h>
#include <math.h>

#define BB 2
#define TT 12
#define CC 128
#define NHEAD 4
#define DHH 32
#define NPIX 1024          // 32*32
#define NT (BB*TT)         // 24
#define IMG (CC*NPIX)      // 131072
#define TOT (NT*IMG)       // 3145728

typedef unsigned long long u64;

// ---- scratch (no allocations allowed) ----
__device__ float g_cur[TOT];
__device__ float g_v[TOT];
__device__ float g_ak[BB*NHEAD*TT*NPIX];
__device__ float g_ws[BB*CC*NPIX];
__device__ float g_att[TOT];
__device__ float g_ff1[TOT];
__device__ float g_ff2[TOT];

// ---- f32x2 helpers ----
__device__ __forceinline__ u64 pack2(float lo, float hi) {
    u64 r; asm("mov.b64 %0,{%1,%2};" : "=l"(r) : "f"(lo), "f"(hi)); return r;
}
__device__ __forceinline__ void unpack2(u64 v, float& lo, float& hi) {
    asm("mov.b64 {%0,%1},%2;" : "=f"(lo), "=f"(hi) : "l"(v));
}
__device__ __forceinline__ void fma2(u64& d, u64 a, u64 b) {
    asm("fma.rn.f32x2 %0, %1, %2, %3;" : "=l"(d) : "l"(a), "l"(b), "l"(d));
}
__device__ __forceinline__ void cp_async4(void* smem_dst, const void* gsrc) {
    unsigned s = (unsigned)__cvta_generic_to_shared(smem_dst);
    asm volatile("cp.async.ca.shared.global [%0], [%1], 4;" :: "r"(s), "l"(gsrc));
}
__device__ __forceinline__ void cp_commit() {
    asm volatile("cp.async.commit_group;" ::: "memory");
}
__device__ __forceinline__ void cp_wait_all() {
    asm volatile("cp.async.wait_group 0;" ::: "memory");
}

__device__ __forceinline__ size_t wgidx_calc(int i, int s, int co0, int CIN) {
    int ci = i / 72; int rm = i - ci * 72; int co = rm / 9; int k = rm - co * 9;
    return (((size_t)(co0 + co) * CIN) + 4 * s + ci) * 9 + k;
}

// ============================================================
// 3x3 SAME conv via packed f32x2 FMA, double-buffered cp.async pipeline.
// GROUPS=1: 128->128 dense (ff). GROUPS=4: per-head 32->32 (kv).
// grid: (24 images, 16 co-groups of 8), block 128, 3 blocks/SM.
// Thread: 2 rows x 4 cols = 8 pixels, 8 co -> 32 f32x2 accumulators.
// ============================================================
template<int GROUPS, bool RELU, bool RES>
__global__ __launch_bounds__(128, 3)
void conv3x3_kernel(const float* __restrict__ in, const float* __restrict__ wgt,
                    const float* __restrict__ bias, const float* __restrict__ res,
                    float* __restrict__ out)
{
    constexpr int CIN = 128 / GROUPS;
    constexpr int S   = CIN / 4;           // pipeline stages (4 planes each)
    __shared__ __align__(16) float splane[2][4 * 1156];   // halo-padded 34x34
    __shared__ u64 swgt[2][4 * 8 * 9];     // [buf][ci][co][k], duplicated (w,w)

    const int n   = blockIdx.x;
    const int co0 = blockIdx.y * 8;
    const int group    = (blockIdx.y * 8) / CIN;
    const int cin_base = group * CIN;
    const int tid = threadIdx.x;
    const int pr2 = (tid >> 3) * 2;        // output rows pr2, pr2+1
    const int pc  = (tid & 7) * 4;         // output cols pc..pc+3

    const float* inp = in + (size_t)n * IMG + (size_t)cin_base * NPIX;

    // zero both buffers (halo ring; interior overwritten each stage)
    for (int i = tid; i < 4 * 1156; i += 128) { splane[0][i] = 0.f; splane[1][i] = 0.f; }

    // ---- per-thread weight slice indices (288 weights total per stage)
    const int wi0 = tid, wi1 = tid + 128, wi2 = tid + 256;   // wi2 valid if tid<32

    // plain lambdas in device code need no annotation
    auto stage_planes = [&](int s) {
        float* dst = splane[s & 1];
        const float* src = inp + (size_t)(4 * s) * NPIX;
        #pragma unroll
        for (int it = 0; it < 32; ++it) {
            int i  = it * 128 + tid;
            int pl = i >> 10, px = i & 1023;
            int r  = px >> 5, c = px & 31;
            cp_async4(&dst[pl * 1156 + (r + 1) * 34 + (c + 1)], &src[pl * NPIX + px]);
        }
        cp_commit();
    };

    u64 acc[8][4];
    #pragma unroll
    for (int co = 0; co < 8; ++co)
        #pragma unroll
        for (int a = 0; a < 4; ++a) acc[co][a] = 0ull;

    // ---- prologue ----
    float wr0, wr1, wr2;
    stage_planes(0);
    wr0 = wgt[wgidx_calc(wi0, 0, co0, CIN)];
    wr1 = wgt[wgidx_calc(wi1, 0, co0, CIN)];
    wr2 = (tid < 32) ? wgt[wgidx_calc(wi2, 0, co0, CIN)] : 0.f;
    swgt[0][wi0] = pack2(wr0, wr0);
    swgt[0][wi1] = pack2(wr1, wr1);
    if (tid < 32) swgt[0][wi2] = pack2(wr2, wr2);
    if (S > 1) {
        wr0 = wgt[wgidx_calc(wi0, 1, co0, CIN)];
        wr1 = wgt[wgidx_calc(wi1, 1, co0, CIN)];
        if (tid < 32) wr2 = wgt[wgidx_calc(wi2, 1, co0, CIN)];
    }
    cp_wait_all();
    __syncthreads();

    for (int s = 0; s < S; ++s) {
        if (s + 1 < S) {
            // stage weights for s+1 (loaded last iteration, latency hidden)
            u64* swb = swgt[(s + 1) & 1];
            swb[wi0] = pack2(wr0, wr0);
            swb[wi1] = pack2(wr1, wr1);
            if (tid < 32) swb[wi2] = pack2(wr2, wr2);
            if (s + 2 < S) {
                wr0 = wgt[wgidx_calc(wi0, s + 2, co0, CIN)];
                wr1 = wgt[wgidx_calc(wi1, s + 2, co0, CIN)];
                if (tid < 32) wr2 = wgt[wgidx_calc(wi2, s + 2, co0, CIN)];
            }
            stage_planes(s + 1);
        }

        // ---- compute stage s ----
        const float* pb = splane[s & 1];
        const u64*   wb = swgt[s & 1];
        #pragma unroll
        for (int ci = 0; ci < 4; ++ci) {
            const float* pl = &pb[ci * 1156];
            u64 prs[4][5];
            #pragma unroll
            for (int r = 0; r < 4; ++r) {
                const u64* p64 = reinterpret_cast<const u64*>(pl + (pr2 + r) * 34 + pc);
                u64 a0 = p64[0], a1 = p64[1], a2 = p64[2];
                float f0, f1, f2, f3, f4, f5;
                unpack2(a0, f0, f1); unpack2(a1, f2, f3); unpack2(a2, f4, f5);
                prs[r][0] = a0; prs[r][2] = a1; prs[r][4] = a2;
                prs[r][1] = pack2(f1, f2); prs[r][3] = pack2(f3, f4);
            }
            #pragma unroll
            for (int co = 0; co < 8; ++co) {
                const u64* wp = &wb[(ci * 8 + co) * 9];
                u64 w[9];
                #pragma unroll
                for (int k = 0; k < 9; ++k) w[k] = wp[k];
                #pragma unroll
                for (int ry = 0; ry < 2; ++ry)
                    #pragma unroll
                    for (int pp = 0; pp < 2; ++pp) {
                        u64 a = acc[co][ry * 2 + pp];
                        #pragma unroll
                        for (int kr = 0; kr < 3; ++kr)
                            #pragma unroll
                            for (int kc = 0; kc < 3; ++kc)
                                fma2(a, w[kr * 3 + kc], prs[ry + kr][kc + 2 * pp]);
                        acc[co][ry * 2 + pp] = a;
                    }
            }
        }
        if (s + 1 < S) { cp_wait_all(); __syncthreads(); }
    }

    #pragma unroll
    for (int co = 0; co < 8; ++co) {
        const float bv = bias[co0 + co];
        #pragma unroll
        for (int ry = 0; ry < 2; ++ry)
            #pragma unroll
            for (int pp = 0; pp < 2; ++pp) {
                float v0, v1;
                unpack2(acc[co][ry * 2 + pp], v0, v1);
                v0 += bv; v1 += bv;
                if (RELU) { v0 = fmaxf(v0, 0.f); v1 = fmaxf(v1, 0.f); }
                size_t oidx = (size_t)n * IMG + (size_t)(co0 + co) * NPIX
                            + (pr2 + ry) * 32 + pc + pp * 2;
                if (RES) { v0 += res[oidx]; v1 += res[oidx + 1]; }
                out[oidx]     = v0;
                out[oidx + 1] = v1;
            }
    }
}

// ============================================================
// attention-key logits: ak[b,head,t,pix] = conv3x3(v + pos, attw_k[head])
// ============================================================
__global__ __launch_bounds__(256)
void ak_kernel(const float* __restrict__ v, const float* __restrict__ attw,
               float* __restrict__ ak)
{
    __shared__ float splane[34*34];
    __shared__ float sw[9];

    const int bth  = blockIdx.x;
    const int head = bth & 3;
    const int bt   = bth >> 2;
    const int b    = bt / TT;
    const int t    = bt % TT;
    const int tid  = threadIdx.x;
    const int pr   = tid >> 3;
    const int pc   = (tid & 7) * 4;

    float acc[4] = {0.f, 0.f, 0.f, 0.f};

    for (int ci = 0; ci < 32; ++ci) {
        const int   ii   = ci >> 1;
        const float div  = __expf(-(float)ii * (logf(10000.0f) / 16.0f));
        const float ang  = (float)t * div;
        const float posv = (ci & 1) ? cosf(ang) : sinf(ang);

        const float* pl = v + ((size_t)bt * CC + head * DHH + ci) * NPIX;
        for (int idx = tid; idx < 34*34; idx += 256) {
            int r = idx / 34 - 1, c = idx % 34 - 1;
            splane[idx] = (r >= 0 && r < 32 && c >= 0 && c < 32) ? (pl[r*32 + c] + posv) : 0.f;
        }
        if (tid < 9)
            sw[tid] = attw[((head * 64) + 32 + ci) * 9 + tid];
        __syncthreads();

        float nb[3][6];
        #pragma unroll
        for (int r = 0; r < 3; ++r)
            #pragma unroll
            for (int c = 0; c < 6; ++c)
                nb[r][c] = splane[(pr + r) * 34 + pc + c];

        const float w0 = sw[0], w1 = sw[1], w2 = sw[2];
        const float w3 = sw[3], w4 = sw[4], w5 = sw[5];
        const float w6 = sw[6], w7 = sw[7], w8 = sw[8];
        #pragma unroll
        for (int p = 0; p < 4; ++p) {
            float s = acc[p];
            s += w0*nb[0][p] + w1*nb[0][p+1] + w2*nb[0][p+2];
            s += w3*nb[1][p] + w4*nb[1][p+1] + w5*nb[1][p+2];
            s += w6*nb[2][p] + w7*nb[2][p+1] + w8*nb[2][p+2];
            acc[p] = s;
        }
        __syncthreads();
    }

    #pragma unroll
    for (int p = 0; p < 4; ++p)
        ak[(((size_t)(b * NHEAD + head) * TT) + t) * NPIX + pr * 32 + pc + p] = acc[p];
}

// ============================================================
// softmax over key frames + weighted sum of v (query-independent; q path
// and attention bias cancel exactly in softmax). Channel-chunked x4.
// ============================================================
__global__ __launch_bounds__(256)
void softmax_ws_kernel(const float* __restrict__ ak, const float* __restrict__ v,
                       float* __restrict__ ws)
{
    const int chunk = blockIdx.x & 3;                     // 8 channels each
    const int gid   = (blockIdx.x >> 2) * 256 + threadIdx.x;   // 0..8191
    const int pix   = gid & 1023;
    const int head  = (gid >> 10) & 3;
    const int b     = gid >> 12;

    float lg[TT];
    float m = -1e30f;
    #pragma unroll
    for (int t = 0; t < TT; ++t) {
        lg[t] = ak[(((size_t)(b * NHEAD + head) * TT) + t) * NPIX + pix];
        m = fmaxf(m, lg[t]);
    }
    float s = 0.f;
    #pragma unroll
    for (int t = 0; t < TT; ++t) { lg[t] = expf(lg[t] - m); s += lg[t]; }
    const float inv = 1.f / s;

    const int c0 = chunk * 8;
    #pragma unroll
    for (int cc = 0; cc < 8; ++cc) {
        int c = c0 + cc;
        float a = 0.f;
        #pragma unroll
        for (int t = 0; t < TT; ++t)
            a += lg[t] * v[((size_t)(b * TT + t) * CC + head * DHH + c) * NPIX + pix];
        ws[((size_t)b * CC + head * DHH + c) * NPIX + pix] = a * inv;
    }
}

// att_out[b,i,c,pix] = cur[b,i,c,pix] + ws[b,c,pix]
__global__ __launch_bounds__(256)
void add_ws_kernel(const float* __restrict__ cur, const float* __restrict__ ws,
                   float* __restrict__ out)
{
    const size_t idx = (size_t)blockIdx.x * 256 + threadIdx.x;
    if (idx >= TOT) return;
    const int pix = (int)(idx & 1023);
    const int c   = (int)((idx >> 10) & 127);
    const int bt  = (int)(idx >> 17);
    const int b   = bt / TT;
    out[idx] = cur[idx] + ws[((size_t)b * CC + c) * NPIX + pix];
}

// ============================================================
// GroupNorm: 4 groups of 32 channels over 32*1024 elems.
// ============================================================
__global__ __launch_bounds__(256)
void groupnorm_kernel(const float* __restrict__ in, const float* __restrict__ gnw,
                      const float* __restrict__ gnb, float* __restrict__ out)
{
    __shared__ float rs[256], rs2[256];
    const int n  = blockIdx.x >> 2;
    const int g  = blockIdx.x & 3;
    const int tid = threadIdx.x;
    const float* p = in + (size_t)n * IMG + (size_t)g * 32 * NPIX;

    float s = 0.f, s2 = 0.f;
    for (int i = tid; i < 32 * NPIX; i += 256) {
        float x = p[i];
        s += x; s2 += x * x;
    }
    rs[tid] = s; rs2[tid] = s2;
    __syncthreads();
    for (int off = 128; off > 0; off >>= 1) {
        if (tid < off) { rs[tid] += rs[tid + off]; rs2[tid] += rs2[tid + off]; }
        __syncthreads();
    }
    const float mean = rs[0] * (1.f / 32768.f);
    const float var  = rs2[0] * (1.f / 32768.f) - mean * mean;
    const float rstd = rsqrtf(var + 1e-5f);

    float* o = out + (size_t)n * IMG + (size_t)g * 32 * NPIX;
    for (int i = tid; i < 32 * NPIX; i += 256) {
        int c = g * 32 + (i >> 10);
        o[i] = (p[i] - mean) * rstd * gnw[c] + gnb[c];
    }
}

// ============================================================
extern "C" void kernel_launch(void* const* d_in, const int* in_sizes, int n_in,
                              void* d_out, int out_size)
{
    const float* x0   = (const float*)d_in[0];
    // d_in[1]=q_w, d_in[2]=q_b, d_in[6]=att_b : cancel exactly in the softmax
    const float* kvw  = (const float*)d_in[3];
    const float* kvb  = (const float*)d_in[4];
    const float* attw = (const float*)d_in[5];
    const float* ff1w = (const float*)d_in[7];
    const float* ff1b = (const float*)d_in[8];
    const float* ff2w = (const float*)d_in[9];
    const float* ff2b = (const float*)d_in[10];
    const float* gnw  = (const float*)d_in[11];
    const float* gnb  = (const float*)d_in[12];

    float *cur, *v, *ak, *ws, *att, *ff1, *ff2;
    cudaGetSymbolAddress((void**)&cur, g_cur);
    cudaGetSymbolAddress((void**)&v,   g_v);
    cudaGetSymbolAddress((void**)&ak,  g_ak);
    cudaGetSymbolAddress((void**)&ws,  g_ws);
    cudaGetSymbolAddress((void**)&att, g_att);
    cudaGetSymbolAddress((void**)&ff1, g_ff1);
    cudaGetSymbolAddress((void**)&ff2, g_ff2);

    const float* lin = x0;
    for (int l = 0; l < 5; ++l) {
        conv3x3_kernel<4, false, false><<<dim3(NT, 16), 128>>>(
            lin, kvw + (size_t)l * 4 * 32 * 32 * 9, kvb + l * 128, nullptr, v);
        ak_kernel<<<NT * NHEAD, 256>>>(v, attw + (size_t)l * 4 * 64 * 9, ak);
        softmax_ws_kernel<<<128, 256>>>(ak, v, ws);
        add_ws_kernel<<<TOT / 256, 256>>>(lin, ws, att);
        conv3x3_kernel<1, true, false><<<dim3(NT, 16), 128>>>(
            att, ff1w + (size_t)l * 128 * 128 * 9, ff1b + l * 128, nullptr, ff1);
        conv3x3_kernel<1, false, true><<<dim3(NT, 16), 128>>>(
            ff1, ff2w + (size_t)l * 128 * 128 * 9, ff2b + l * 128, att, ff2);
        float* lout = (l == 4) ? (float*)d_out : cur;
        groupnorm_kernel<<<NT * 4, 256>>>(ff2, gnw + l * 128, gnb + l * 128, lout);
        lin = cur;
    }
}

// round 7
// speedup vs baseline: 1.2902x; 1.2902x over previous
#include <cuda_runtime.h>
#include <cuda_bf16.h>
#include <math.h>
#include <stdint.h>

#define BB 2
#define TT 12
#define CC 128
#define NHEAD 4
#define DHH 32
#define NPIX 1024
#define NT (BB*TT)
#define IMG (CC*NPIX)
#define TOT (NT*IMG)

// Y: channel-last haloed split activations: [img 24][pix34 1156][256 bf16]
//    per pixel: 4 chunks x (32 hi | 32 lo) bf16 = 512B
#define YTOT (NT*1156*256)
// Wp: [conv 15][sh 9][ch 4][var 2][co 128][64 bf16]
#define WPERCONV (9*4*2*128*64)
#define WPTOT (15*WPERCONV)

// ---- scratch ----
__device__ float g_cur[TOT];
__device__ float g_v[TOT];
__device__ float g_ak[BB*NHEAD*TT*NPIX];
__device__ float g_ws[BB*CC*NPIX];
__device__ float g_att[TOT];
__device__ float g_ff1[TOT];
__device__ float g_ff2[TOT];
__device__ __nv_bfloat16 g_Y[YTOT];
__device__ __nv_bfloat16 g_Wp[WPTOT];

// ---- smem layout for conv kernel (dynamic) ----
#define BBUF 48960            // 340 rows * 144B
#define WBUF 36864            // 2 var * 128 co * 144B
#define WOFF (2*BBUF)         // 97920
#define CSMEM (2*BBUF + 2*WBUF)   // 171648

// ---- PTX helpers (baseline sm_80+ features only; no tcgen05 on sm_103 target) ----
__device__ __forceinline__ void cp16(void* d, const void* s) {
    unsigned a = (unsigned)__cvta_generic_to_shared(d);
    asm volatile("cp.async.cg.shared.global [%0], [%1], 16;" :: "r"(a), "l"(s));
}
__device__ __forceinline__ void cp_commit() { asm volatile("cp.async.commit_group;" ::: "memory"); }
__device__ __forceinline__ void cp_wait0()  { asm volatile("cp.async.wait_group 0;" ::: "memory"); }

__device__ __forceinline__ void ldsm4(uint32_t* r, uint32_t a) {
    asm volatile("ldmatrix.sync.aligned.m8n8.x4.shared.b16 {%0,%1,%2,%3}, [%4];"
        : "=r"(r[0]), "=r"(r[1]), "=r"(r[2]), "=r"(r[3]) : "r"(a));
}
__device__ __forceinline__ void ldsm2(uint32_t* r, uint32_t a) {
    asm volatile("ldmatrix.sync.aligned.m8n8.x2.shared.b16 {%0,%1}, [%2];"
        : "=r"(r[0]), "=r"(r[1]) : "r"(a));
}
__device__ __forceinline__ void mma16816(float* d, const uint32_t* a, const uint32_t* b) {
    asm volatile("mma.sync.aligned.m16n8k16.row.col.f32.bf16.bf16.f32 "
        "{%0,%1,%2,%3}, {%4,%5,%6,%7}, {%8,%9}, {%0,%1,%2,%3};"
        : "+f"(d[0]), "+f"(d[1]), "+f"(d[2]), "+f"(d[3])
        : "r"(a[0]), "r"(a[1]), "r"(a[2]), "r"(a[3]), "r"(b[0]), "r"(b[1]));
}

// ============================================================
// weight prep: split bf16 with variant packing
// var0 = [w_hi | w_hi]  (pairs with [x_hi|x_lo] -> x_hi*w_hi + x_lo*w_hi)
// var1 = [w_lo | 0  ]   (-> x_hi*w_lo). Dropped: x_lo*w_lo (~2^-16)
// kv conv expanded block-diagonal into dense 128x128.
// ============================================================
__global__ __launch_bounds__(256)
void wprep_kernel(const float* __restrict__ kvw, const float* __restrict__ ff1w,
                  const float* __restrict__ ff2w, __nv_bfloat16* __restrict__ Wp)
{
    int idx = blockIdx.x * 256 + threadIdx.x;
    if (idx >= WPTOT) return;
    int k   = idx & 63;
    int co  = (idx >> 6) & 127;
    int var = (idx >> 13) & 1;
    int ch  = (idx >> 14) & 3;
    int t   = idx >> 16;                  // conv*9 + sh
    int conv = t / 9, sh = t - conv * 9;
    int l = conv / 3, type = conv - l * 3;
    int kr = sh / 3, kc = sh - kr * 3;
    int cil = k & 31;
    float w;
    if (type == 0) {
        w = ((co >> 5) == ch)
          ? kvw[((((size_t)l * 4 + ch) * 32 + (co & 31)) * 32 + cil) * 9 + kr * 3 + kc]
          : 0.f;
    } else {
        const float* W = (type == 1) ? ff1w : ff2w;
        w = W[(((size_t)l * 128 + co) * 128 + ch * 32 + cil) * 9 + kr * 3 + kc];
    }
    __nv_bfloat16 hi = __float2bfloat16(w);
    __nv_bfloat16 v;
    if (var == 0) v = hi;
    else          v = (k < 32) ? __float2bfloat16(w - __bfloat162float(hi)) : __float2bfloat16(0.f);
    Wp[idx] = v;
}

__global__ __launch_bounds__(256)
void yzero_kernel(unsigned* __restrict__ Y32)
{
    size_t i = (size_t)blockIdx.x * 256 + threadIdx.x;
    if (i < YTOT / 2) Y32[i] = 0u;
}

// ============================================================
// planar fp32 -> Y (channel-last haloed split-bf16), interior only
// ============================================================
__global__ __launch_bounds__(256)
void prep_kernel(const float* __restrict__ x, __nv_bfloat16* __restrict__ Y)
{
    __shared__ float sm[128 * 33];
    const int img = blockIdx.x >> 5;
    const int row = blockIdx.x & 31;
    const int tid = threadIdx.x;
    const int c   = tid & 31;
    const int ci0 = tid >> 5;
    const float* xp = x + (size_t)img * IMG + row * 32;
    #pragma unroll
    for (int k = 0; k < 16; ++k) {
        int ci = ci0 * 16 + k;
        sm[ci * 33 + c] = xp[(size_t)ci * NPIX + c];
    }
    __syncthreads();

    unsigned* out32 = reinterpret_cast<unsigned*>(Y + ((size_t)img * 1156 + (row + 1) * 34 + 1) * 256);
    const int q  = tid & 127;
    const int ph = tid >> 7;
    #pragma unroll
    for (int p = 0; p < 16; ++p) {
        int c2 = p * 2 + ph;
        unsigned pk = 0;
        #pragma unroll
        for (int half = 0; half < 2; ++half) {
            int e  = q * 2 + half;
            int ch = e >> 6, r6 = e & 63;
            float xv = sm[(ch * 32 + (r6 & 31)) * 33 + c2];
            __nv_bfloat16 hi = __float2bfloat16(xv);
            __nv_bfloat16 v  = (r6 >= 32) ? __float2bfloat16(xv - __bfloat162float(hi)) : hi;
            pk |= ((unsigned)__bfloat16_as_ushort(v)) << (16 * half);
        }
        out32[(size_t)c2 * 128 + q] = pk;
    }
}

// ============================================================
// conv via mma.sync (HMMA bf16): D[128co x 256pix] per CTA
// grid 96 = (img, 8-row block), 512 threads = 16 warps (4 co x 4 pix tiles)
// K loop: 4 chunks x 9 shifts x 2 variants x K64
// ============================================================
template<bool RELU, bool RES>
__global__ __launch_bounds__(512, 1)
void conv_mma_kernel(const __nv_bfloat16* __restrict__ Y,
                     const __nv_bfloat16* __restrict__ Wc,
                     const float* __restrict__ bias,
                     const float* __restrict__ res,
                     float* __restrict__ out)
{
    extern __shared__ __align__(16) char smem[];
    const uint32_t sb = (uint32_t)__cvta_generic_to_shared(smem);
    const int tid  = threadIdx.x;
    const int lane = tid & 31;
    const int w    = tid >> 5;
    const int wco  = w >> 2;          // 0..3 -> co stripe of 32
    const int wpx  = w & 3;           // 0..3 -> pixel quarter of 64
    const int img  = blockIdx.x >> 2;
    const int r0   = (blockIdx.x & 3) * 8;

    // ldmatrix lane->address components
    const int arow  = (lane & 7) + ((lane >> 3) & 1) * 8;   // A: row within m16
    const int akoff = (lane >> 4) * 16;                     // A: k-half byte offset
    const int brow  = lane & 7;                             // B: row within n8
    const int bkoff = ((lane >> 3) & 1) * 16;               // B: k-half byte offset

    const char* Yb = (const char*)Y;
    const char* Wb = (const char*)Wc;

    auto stage_B = [&](int ch) {
        char* dst = smem + (ch & 1) * BBUF;
        const size_t ybase = (size_t)img * 1156 * 512 + (size_t)ch * 128;
        for (int i = tid; i < 2720; i += 512) {
            int row = i >> 3, c16 = i & 7;
            int hr = row / 34, hc = row - hr * 34;
            cp16(dst + row * 144 + c16 * 16,
                 Yb + ybase + ((size_t)(r0 + hr) * 34 + hc) * 512 + c16 * 16);
        }
    };
    auto stage_A = [&](int it) {
        int ch = it / 9, sh = it - ch * 9;
        char* dst = smem + WOFF + (it & 1) * WBUF;
        const char* src = Wb + (size_t)((sh * 4 + ch) * 2) * 16384;
        #pragma unroll
        for (int k = 0; k < 4; ++k) {
            int i = k * 512 + tid;           // 0..2047
            int var = i >> 10, co = (i >> 3) & 127, c16 = i & 7;
            cp16(dst + (var * 128 + co) * 144 + c16 * 16,
                 src + (size_t)(var * 8192 + co * 64 + c16 * 8) * 2);
        }
    };

    float acc[2][8][4];
    #pragma unroll
    for (int m = 0; m < 2; ++m)
        #pragma unroll
        for (int j = 0; j < 8; ++j)
            #pragma unroll
            for (int q = 0; q < 4; ++q) acc[m][j][q] = 0.f;

    stage_B(0);
    stage_A(0);
    cp_commit();
    cp_wait0();
    __syncthreads();

    for (int it = 0; it < 36; ++it) {
        const int ch = it / 9, sh = it - ch * 9;
        if (it + 1 < 36) {
            stage_A(it + 1);
            if (sh == 8) stage_B(ch + 1);
            cp_commit();
        }

        // ---- compute (ch, sh) ----
        const int dr = sh / 3, dc = sh - dr * 3;
        const uint32_t bbase = sb + (ch & 1) * BBUF;
        const uint32_t abase = sb + WOFF + (it & 1) * WBUF;
        uint32_t baddr[8];
        #pragma unroll
        for (int j = 0; j < 8; ++j) {
            int rowj = (wpx * 2 + (j >> 2) + dr) * 34 + (j & 3) * 8 + dc + brow;
            baddr[j] = bbase + rowj * 144 + bkoff;
        }
        const uint32_t aA = abase + (wco * 32 + arow) * 144 + akoff;

        #pragma unroll
        for (int ks = 0; ks < 4; ++ks) {
            uint32_t bfr[8][2];
            #pragma unroll
            for (int j = 0; j < 8; ++j) ldsm2(bfr[j], baddr[j] + ks * 32);
            #pragma unroll
            for (int var = 0; var < 2; ++var) {
                uint32_t a0[4], a1[4];
                ldsm4(a0, aA + var * (128 * 144) + ks * 32);
                ldsm4(a1, aA + var * (128 * 144) + 16 * 144 + ks * 32);
                #pragma unroll
                for (int j = 0; j < 8; ++j) {
                    mma16816(acc[0][j], a0, bfr[j]);
                    mma16816(acc[1][j], a1, bfr[j]);
                }
            }
        }
        if (it + 1 < 36) { cp_wait0(); __syncthreads(); }
    }

    // ---- epilogue ----
    #pragma unroll
    for (int m = 0; m < 2; ++m) {
        const int cobase = wco * 32 + m * 16 + (lane >> 2);
        const float b0 = bias[cobase], b1 = bias[cobase + 8];
        #pragma unroll
        for (int j = 0; j < 8; ++j) {
            const int gp = r0 * 32 + wpx * 64 + j * 8 + (lane & 3) * 2;
            {
                float v0 = acc[m][j][0] + b0, v1 = acc[m][j][1] + b0;
                if (RELU) { v0 = fmaxf(v0, 0.f); v1 = fmaxf(v1, 0.f); }
                size_t o = ((size_t)img * CC + cobase) * NPIX + gp;
                if (RES) { v0 += res[o]; v1 += res[o + 1]; }
                out[o] = v0; out[o + 1] = v1;
            }
            {
                float v0 = acc[m][j][2] + b1, v1 = acc[m][j][3] + b1;
                if (RELU) { v0 = fmaxf(v0, 0.f); v1 = fmaxf(v1, 0.f); }
                size_t o = ((size_t)img * CC + cobase + 8) * NPIX + gp;
                if (RES) { v0 += res[o]; v1 += res[o + 1]; }
                out[o] = v0; out[o + 1] = v1;
            }
        }
    }
}

// ============================================================
// ak / softmax_ws / add_ws / groupnorm (known-correct)
// ============================================================
__global__ __launch_bounds__(256)
void ak_kernel(const float* __restrict__ v, const float* __restrict__ attw,
               float* __restrict__ ak)
{
    __shared__ float splane[34*34];
    __shared__ float sw[9];
    const int head = blockIdx.x & 3, bt = blockIdx.x >> 2;
    const int b = bt / TT, t = bt % TT;
    const int tid = threadIdx.x, pr = tid >> 3, pc = (tid & 7) * 4;
    float acc[4] = {0.f, 0.f, 0.f, 0.f};

    for (int ci = 0; ci < 32; ++ci) {
        const float div  = __expf(-(float)(ci >> 1) * (logf(10000.0f) / 16.0f));
        const float ang  = (float)t * div;
        const float posv = (ci & 1) ? cosf(ang) : sinf(ang);
        const float* pl = v + ((size_t)bt * CC + head * DHH + ci) * NPIX;
        for (int idx = tid; idx < 34*34; idx += 256) {
            int r = idx / 34 - 1, c = idx % 34 - 1;
            splane[idx] = (r >= 0 && r < 32 && c >= 0 && c < 32) ? (pl[r*32 + c] + posv) : 0.f;
        }
        if (tid < 9) sw[tid] = attw[((head * 64) + 32 + ci) * 9 + tid];
        __syncthreads();
        float nb[3][6];
        #pragma unroll
        for (int r = 0; r < 3; ++r)
            #pragma unroll
            for (int c = 0; c < 6; ++c) nb[r][c] = splane[(pr + r) * 34 + pc + c];
        const float w0=sw[0],w1=sw[1],w2=sw[2],w3=sw[3],w4=sw[4],w5=sw[5],w6=sw[6],w7=sw[7],w8=sw[8];
        #pragma unroll
        for (int p = 0; p < 4; ++p) {
            float s = acc[p];
            s += w0*nb[0][p] + w1*nb[0][p+1] + w2*nb[0][p+2];
            s += w3*nb[1][p] + w4*nb[1][p+1] + w5*nb[1][p+2];
            s += w6*nb[2][p] + w7*nb[2][p+1] + w8*nb[2][p+2];
            acc[p] = s;
        }
        __syncthreads();
    }
    #pragma unroll
    for (int p = 0; p < 4; ++p)
        ak[(((size_t)(b * NHEAD + head) * TT) + t) * NPIX + pr * 32 + pc + p] = acc[p];
}

__global__ __launch_bounds__(256)
void softmax_ws_kernel(const float* __restrict__ ak, const float* __restrict__ v,
                       float* __restrict__ ws)
{
    const int chunk = blockIdx.x & 3;
    const int gid   = (blockIdx.x >> 2) * 256 + threadIdx.x;
    const int pix = gid & 1023, head = (gid >> 10) & 3, b = gid >> 12;
    float lg[TT], m = -1e30f;
    #pragma unroll
    for (int t = 0; t < TT; ++t) {
        lg[t] = ak[(((size_t)(b * NHEAD + head) * TT) + t) * NPIX + pix];
        m = fmaxf(m, lg[t]);
    }
    float s = 0.f;
    #pragma unroll
    for (int t = 0; t < TT; ++t) { lg[t] = expf(lg[t] - m); s += lg[t]; }
    const float inv = 1.f / s;
    const int c0 = chunk * 8;
    #pragma unroll
    for (int cc = 0; cc < 8; ++cc) {
        int c = c0 + cc;
        float a = 0.f;
        #pragma unroll
        for (int t = 0; t < TT; ++t)
            a += lg[t] * v[((size_t)(b * TT + t) * CC + head * DHH + c) * NPIX + pix];
        ws[((size_t)b * CC + head * DHH + c) * NPIX + pix] = a * inv;
    }
}

__global__ __launch_bounds__(256)
void add_ws_kernel(const float* __restrict__ cur, const float* __restrict__ ws,
                   float* __restrict__ out)
{
    const size_t idx = (size_t)blockIdx.x * 256 + threadIdx.x;
    if (idx >= TOT) return;
    const int pix = (int)(idx & 1023);
    const int c   = (int)((idx >> 10) & 127);
    const int b   = (int)(idx >> 17) / TT;
    out[idx] = cur[idx] + ws[((size_t)b * CC + c) * NPIX + pix];
}

__global__ __launch_bounds__(256)
void groupnorm_kernel(const float* __restrict__ in, const float* __restrict__ gnw,
                      const float* __restrict__ gnb, float* __restrict__ out)
{
    __shared__ float rs[256], rs2[256];
    const int n = blockIdx.x >> 2, g = blockIdx.x & 3, tid = threadIdx.x;
    const float* p = in + (size_t)n * IMG + (size_t)g * 32 * NPIX;
    float s = 0.f, s2 = 0.f;
    for (int i = tid; i < 32 * NPIX; i += 256) { float x = p[i]; s += x; s2 += x * x; }
    rs[tid] = s; rs2[tid] = s2;
    __syncthreads();
    for (int off = 128; off > 0; off >>= 1) {
        if (tid < off) { rs[tid] += rs[tid + off]; rs2[tid] += rs2[tid + off]; }
        __syncthreads();
    }
    const float mean = rs[0] * (1.f / 32768.f);
    const float var  = rs2[0] * (1.f / 32768.f) - mean * mean;
    const float rstd = rsqrtf(var + 1e-5f);
    float* o = out + (size_t)n * IMG + (size_t)g * 32 * NPIX;
    for (int i = tid; i < 32 * NPIX; i += 256) {
        int c = g * 32 + (i >> 10);
        o[i] = (p[i] - mean) * rstd * gnw[c] + gnb[c];
    }
}

// ============================================================
extern "C" void kernel_launch(void* const* d_in, const int* in_sizes, int n_in,
                              void* d_out, int out_size)
{
    const float* x0   = (const float*)d_in[0];
    // q_w, q_b, att_b cancel exactly in the softmax
    const float* kvw  = (const float*)d_in[3];
    const float* kvb  = (const float*)d_in[4];
    const float* attw = (const float*)d_in[5];
    const float* ff1w = (const float*)d_in[7];
    const float* ff1b = (const float*)d_in[8];
    const float* ff2w = (const float*)d_in[9];
    const float* ff2b = (const float*)d_in[10];
    const float* gnw  = (const float*)d_in[11];
    const float* gnb  = (const float*)d_in[12];

    float *cur, *v, *ak, *ws, *att, *ff1, *ff2;
    __nv_bfloat16 *Y, *Wp;
    cudaGetSymbolAddress((void**)&cur, g_cur);
    cudaGetSymbolAddress((void**)&v,   g_v);
    cudaGetSymbolAddress((void**)&ak,  g_ak);
    cudaGetSymbolAddress((void**)&ws,  g_ws);
    cudaGetSymbolAddress((void**)&att, g_att);
    cudaGetSymbolAddress((void**)&ff1, g_ff1);
    cudaGetSymbolAddress((void**)&ff2, g_ff2);
    cudaGetSymbolAddress((void**)&Y,   g_Y);
    cudaGetSymbolAddress((void**)&Wp,  g_Wp);

    cudaFuncSetAttribute(conv_mma_kernel<false,false>, cudaFuncAttributeMaxDynamicSharedMemorySize, CSMEM);
    cudaFuncSetAttribute(conv_mma_kernel<true, false>, cudaFuncAttributeMaxDynamicSharedMemorySize, CSMEM);
    cudaFuncSetAttribute(conv_mma_kernel<false,true >, cudaFuncAttributeMaxDynamicSharedMemorySize, CSMEM);

    wprep_kernel<<<(WPTOT + 255) / 256, 256>>>(kvw, ff1w, ff2w, Wp);
    yzero_kernel<<<(YTOT / 2 + 255) / 256, 256>>>((unsigned*)Y);

    const float* lin = x0;
    for (int l = 0; l < 5; ++l) {
        prep_kernel<<<NT * 32, 256>>>(lin, Y);
        conv_mma_kernel<false,false><<<96, 512, CSMEM>>>(
            Y, Wp + (size_t)(l * 3 + 0) * WPERCONV, kvb + l * 128, nullptr, v);
        ak_kernel<<<NT * NHEAD, 256>>>(v, attw + (size_t)l * 4 * 64 * 9, ak);
        softmax_ws_kernel<<<128, 256>>>(ak, v, ws);
        add_ws_kernel<<<TOT / 256, 256>>>(lin, ws, att);
        prep_kernel<<<NT * 32, 256>>>(att, Y);
        conv_mma_kernel<true,false><<<96, 512, CSMEM>>>(
            Y, Wp + (size_t)(l * 3 + 1) * WPERCONV, ff1b + l * 128, nullptr, ff1);
        prep_kernel<<<NT * 32, 256>>>(ff1, Y);
        conv_mma_kernel<false,true><<<96, 512, CSMEM>>>(
            Y, Wp + (size_t)(l * 3 + 2) * WPERCONV, ff2b + l * 128, att, ff2);
        float* lout = (l == 4) ? (float*)d_out : cur;
        groupnorm_kernel<<<NT * 4, 256>>>(ff2, gnw + l * 128, gnb + l * 128, lout);
        lin = cur;
    }
}

// round 8
// speedup vs baseline: 1.7572x; 1.3620x over previous
#include <cuda_runtime.h>
#include <cuda_bf16.h>
#include <math.h>
#include <stdint.h>

#define BB 2
#define TT 12
#define CC 128
#define NHEAD 4
#define DHH 32
#define NPIX 1024
#define NT (BB*TT)
#define IMG (CC*NPIX)
#define TOT (NT*IMG)

// Y: channel-last haloed split activations: [img 24][pix34 1156][256 bf16]
#define YTOT (NT*1156*256)
// Wp per conv: [sh*4+ch 36] x (var0: 128co x 64K | var1: 128co x 32K) = 36*12288
#define WPERSHCH 12288
#define WPERCONV (36*WPERSHCH)
#define WPTOT (15*WPERCONV)

// ---- scratch ----
__device__ float g_cur[TOT];
__device__ float g_v[TOT];
__device__ float g_ak[BB*NHEAD*TT*NPIX];
__device__ float g_ws[BB*CC*NPIX];
__device__ float g_att[TOT];
__device__ float g_ff1[TOT];
__device__ float g_ff2[TOT];
__device__ __nv_bfloat16 g_Y[YTOT];
__device__ __nv_bfloat16 g_Wp[WPTOT];

// ---- smem layout for conv kernel (dynamic) ----
#define BBUF 48960                 // 340 pixel-rows * 144B
#define V1OFF 18432                // var0: 128 rows * 144B
#define WBUF 28672                 // + var1: 128 rows * 80B
#define WOFF (2*BBUF)              // 97920
#define CSMEM (2*BBUF + 2*WBUF)    // 155264

// ---- PTX helpers (baseline PTX features only; no tcgen05 on sm_103 target) ----
__device__ __forceinline__ void cp16(void* d, const void* s) {
    unsigned a = (unsigned)__cvta_generic_to_shared(d);
    asm volatile("cp.async.cg.shared.global [%0], [%1], 16;" :: "r"(a), "l"(s));
}
__device__ __forceinline__ void cp_commit() { asm volatile("cp.async.commit_group;" ::: "memory"); }
__device__ __forceinline__ void cp_wait0()  { asm volatile("cp.async.wait_group 0;" ::: "memory"); }

__device__ __forceinline__ void ldsm4(uint32_t* r, uint32_t a) {
    asm volatile("ldmatrix.sync.aligned.m8n8.x4.shared.b16 {%0,%1,%2,%3}, [%4];"
        : "=r"(r[0]), "=r"(r[1]), "=r"(r[2]), "=r"(r[3]) : "r"(a));
}
__device__ __forceinline__ void ldsm2(uint32_t* r, uint32_t a) {
    asm volatile("ldmatrix.sync.aligned.m8n8.x2.shared.b16 {%0,%1}, [%2];"
        : "=r"(r[0]), "=r"(r[1]) : "r"(a));
}
__device__ __forceinline__ void mma16816(float* d, const uint32_t* a, const uint32_t* b) {
    asm volatile("mma.sync.aligned.m16n8k16.row.col.f32.bf16.bf16.f32 "
        "{%0,%1,%2,%3}, {%4,%5,%6,%7}, {%8,%9}, {%0,%1,%2,%3};"
        : "+f"(d[0]), "+f"(d[1]), "+f"(d[2]), "+f"(d[3])
        : "r"(a[0]), "r"(a[1]), "r"(a[2]), "r"(a[3]), "r"(b[0]), "r"(b[1]));
}

// ============================================================
// weight prep:
// var0 (K64) = [w_hi | w_hi] pairing with [x_hi | x_lo]
// var1 (K32) = [w_lo] pairing with [x_hi]   (dropped: x_lo*w_lo ~2^-16)
// kv conv expanded block-diagonal into dense 128x128 (zeros off-diagonal).
// ============================================================
__global__ __launch_bounds__(256)
void wprep_kernel(const float* __restrict__ kvw, const float* __restrict__ ff1w,
                  const float* __restrict__ ff2w, __nv_bfloat16* __restrict__ Wp)
{
    int idx = blockIdx.x * 256 + threadIdx.x;
    if (idx >= WPTOT) return;
    int conv = idx / WPERCONV;
    int o    = idx - conv * WPERCONV;
    int t    = o / WPERSHCH;           // sh*4 + ch
    int r    = o - t * WPERSHCH;
    int sh = t >> 2, ch = t & 3;
    int l = conv / 3, type = conv - l * 3;
    int kr = sh / 3, kc = sh - kr * 3;
    int var, co, k;
    if (r < 8192) { var = 0; co = r >> 6; k = r & 63; }
    else          { var = 1; int r2 = r - 8192; co = r2 >> 5; k = r2 & 31; }
    int cil = k & 31;
    float w;
    if (type == 0) {
        w = ((co >> 5) == ch)
          ? kvw[((((size_t)l * 4 + ch) * 32 + (co & 31)) * 32 + cil) * 9 + kr * 3 + kc]
          : 0.f;
    } else {
        const float* W = (type == 1) ? ff1w : ff2w;
        w = W[(((size_t)l * 128 + co) * 128 + ch * 32 + cil) * 9 + kr * 3 + kc];
    }
    __nv_bfloat16 hi = __float2bfloat16(w);
    Wp[idx] = (var == 0) ? hi : __float2bfloat16(w - __bfloat162float(hi));
}

__global__ __launch_bounds__(256)
void yzero_kernel(unsigned* __restrict__ Y32)
{
    size_t i = (size_t)blockIdx.x * 256 + threadIdx.x;
    if (i < YTOT / 2) Y32[i] = 0u;
}

// ============================================================
// planar fp32 -> Y (channel-last haloed split-bf16), interior only
// ADD: if WS, input = cur + ws (frame-broadcast) and also write att (planar)
// ============================================================
template<bool WS>
__global__ __launch_bounds__(256)
void prep_kernel(const float* __restrict__ x, const float* __restrict__ ws,
                 float* __restrict__ att, __nv_bfloat16* __restrict__ Y)
{
    __shared__ float sm[128 * 33];
    const int img = blockIdx.x >> 5;
    const int row = blockIdx.x & 31;
    const int tid = threadIdx.x;
    const int c   = tid & 31;
    const int ci0 = tid >> 5;
    const int b   = img / TT;
    const float* xp = x + (size_t)img * IMG + row * 32;
    #pragma unroll
    for (int k = 0; k < 16; ++k) {
        int ci = ci0 * 16 + k;
        float val = xp[(size_t)ci * NPIX + c];
        if (WS) {
            val += ws[((size_t)b * CC + ci) * NPIX + row * 32 + c];
            att[(size_t)img * IMG + (size_t)ci * NPIX + row * 32 + c] = val;
        }
        sm[ci * 33 + c] = val;
    }
    __syncthreads();

    unsigned* out32 = reinterpret_cast<unsigned*>(Y + ((size_t)img * 1156 + (row + 1) * 34 + 1) * 256);
    const int q  = tid & 127;
    const int ph = tid >> 7;
    #pragma unroll
    for (int p = 0; p < 16; ++p) {
        int c2 = p * 2 + ph;
        unsigned pk = 0;
        #pragma unroll
        for (int half = 0; half < 2; ++half) {
            int e  = q * 2 + half;
            int ch = e >> 6, r6 = e & 63;
            float xv = sm[(ch * 32 + (r6 & 31)) * 33 + c2];
            __nv_bfloat16 hi = __float2bfloat16(xv);
            __nv_bfloat16 v  = (r6 >= 32) ? __float2bfloat16(xv - __bfloat162float(hi)) : hi;
            pk |= ((unsigned)__bfloat16_as_ushort(v)) << (16 * half);
        }
        out32[(size_t)c2 * 128 + q] = pk;
    }
}

// ============================================================
// conv via mma.sync (HMMA bf16): D[128co x 256pix] per CTA
// grid 96 = (img, 8-row block), 512 threads = 16 warps (4 co x 4 pix tiles)
// K loop: 4 chunks x 9 shifts x (var0 K64 + var1 K32)
// GROUPED: warp stripe wco computes only chunk ch==wco (kv block-diagonal)
// ============================================================
template<bool GROUPED, bool RELU, bool RES>
__global__ __launch_bounds__(512, 1)
void conv_mma_kernel(const __nv_bfloat16* __restrict__ Y,
                     const __nv_bfloat16* __restrict__ Wc,
                     const float* __restrict__ bias,
                     const float* __restrict__ res,
                     float* __restrict__ out)
{
    extern __shared__ __align__(16) char smem[];
    const uint32_t sb = (uint32_t)__cvta_generic_to_shared(smem);
    const int tid  = threadIdx.x;
    const int lane = tid & 31;
    const int w    = tid >> 5;
    const int wco  = w >> 2;
    const int wpx  = w & 3;
    const int img  = blockIdx.x >> 2;
    const int r0   = (blockIdx.x & 3) * 8;

    const int arow  = (lane & 7) + ((lane >> 3) & 1) * 8;
    const int akoff = (lane >> 4) * 16;
    const int brow  = lane & 7;
    const int bkoff = ((lane >> 3) & 1) * 16;

    const char* Yb = (const char*)Y;
    const char* Wb = (const char*)Wc;

    auto stage_B = [&](int ch) {
        char* dst = smem + (ch & 1) * BBUF;
        const size_t ybase = (size_t)img * 1156 * 512 + (size_t)ch * 128;
        for (int i = tid; i < 2720; i += 512) {
            int row = i >> 3, c16 = i & 7;
            int hr = row / 34, hc = row - hr * 34;
            cp16(dst + row * 144 + c16 * 16,
                 Yb + ybase + ((size_t)(r0 + hr) * 34 + hc) * 512 + c16 * 16);
        }
    };
    auto stage_A = [&](int it) {
        int ch = it / 9, sh = it - ch * 9;
        char* dst = smem + WOFF + (it & 1) * WBUF;
        const char* src = Wb + (size_t)(sh * 4 + ch) * (WPERSHCH * 2);
        #pragma unroll
        for (int k2 = 0; k2 < 3; ++k2) {
            int i = k2 * 512 + tid;
            if (i < 1024) {
                int co = i >> 3, c16 = i & 7;
                cp16(dst + co * 144 + c16 * 16, src + co * 128 + c16 * 16);
            } else {
                int j = i - 1024;
                int co = j >> 2, c16 = j & 3;
                cp16(dst + V1OFF + co * 80 + c16 * 16, src + 16384 + co * 64 + c16 * 16);
            }
        }
    };

    float acc[2][8][4];
    #pragma unroll
    for (int m = 0; m < 2; ++m)
        #pragma unroll
        for (int j = 0; j < 8; ++j)
            #pragma unroll
            for (int q = 0; q < 4; ++q) acc[m][j][q] = 0.f;

    stage_B(0);
    stage_A(0);
    cp_commit();
    cp_wait0();
    __syncthreads();

    for (int it = 0; it < 36; ++it) {
        const int ch = it / 9, sh = it - ch * 9;
        if (it + 1 < 36) {
            stage_A(it + 1);
            if (sh == 8) stage_B(ch + 1);
            cp_commit();
        }

        if (!GROUPED || ch == wco) {
            const int dr = sh / 3, dc = sh - dr * 3;
            const uint32_t bbase = sb + (ch & 1) * BBUF;
            const uint32_t abase = sb + WOFF + (it & 1) * WBUF;
            uint32_t baddr[8];
            #pragma unroll
            for (int j = 0; j < 8; ++j) {
                int rowj = (wpx * 2 + (j >> 2) + dr) * 34 + (j & 3) * 8 + dc + brow;
                baddr[j] = bbase + rowj * 144 + bkoff;
            }
            const uint32_t aA0 = abase + (wco * 32 + arow) * 144 + akoff;
            const uint32_t aA1 = abase + V1OFF + (wco * 32 + arow) * 80 + akoff;

            #pragma unroll
            for (int ks = 0; ks < 4; ++ks) {
                uint32_t bfr[8][2];
                #pragma unroll
                for (int j = 0; j < 8; ++j) ldsm2(bfr[j], baddr[j] + ks * 32);
                uint32_t a0[4], a1[4];
                ldsm4(a0, aA0 + ks * 32);
                ldsm4(a1, aA0 + 16 * 144 + ks * 32);
                #pragma unroll
                for (int j = 0; j < 8; ++j) {
                    mma16816(acc[0][j], a0, bfr[j]);
                    mma16816(acc[1][j], a1, bfr[j]);
                }
                if (ks < 2) {
                    uint32_t c0[4], c1[4];
                    ldsm4(c0, aA1 + ks * 32);
                    ldsm4(c1, aA1 + 16 * 80 + ks * 32);
                    #pragma unroll
                    for (int j = 0; j < 8; ++j) {
                        mma16816(acc[0][j], c0, bfr[j]);
                        mma16816(acc[1][j], c1, bfr[j]);
                    }
                }
            }
        }
        if (it + 1 < 36) { cp_wait0(); __syncthreads(); }
    }

    // ---- epilogue ----
    #pragma unroll
    for (int m = 0; m < 2; ++m) {
        const int cobase = wco * 32 + m * 16 + (lane >> 2);
        const float b0 = bias[cobase], b1 = bias[cobase + 8];
        #pragma unroll
        for (int j = 0; j < 8; ++j) {
            const int gp = r0 * 32 + wpx * 64 + j * 8 + (lane & 3) * 2;
            {
                float v0 = acc[m][j][0] + b0, v1 = acc[m][j][1] + b0;
                if (RELU) { v0 = fmaxf(v0, 0.f); v1 = fmaxf(v1, 0.f); }
                size_t o = ((size_t)img * CC + cobase) * NPIX + gp;
                if (RES) { v0 += res[o]; v1 += res[o + 1]; }
                out[o] = v0; out[o + 1] = v1;
            }
            {
                float v0 = acc[m][j][2] + b1, v1 = acc[m][j][3] + b1;
                if (RELU) { v0 = fmaxf(v0, 0.f); v1 = fmaxf(v1, 0.f); }
                size_t o = ((size_t)img * CC + cobase + 8) * NPIX + gp;
                if (RES) { v0 += res[o]; v1 += res[o + 1]; }
                out[o] = v0; out[o + 1] = v1;
            }
        }
    }
}

// ============================================================
// ak / softmax_ws / groupnorm (known-correct)
// ============================================================
__global__ __launch_bounds__(256)
void ak_kernel(const float* __restrict__ v, const float* __restrict__ attw,
               float* __restrict__ ak)
{
    __shared__ float splane[34*34];
    __shared__ float sw[9];
    const int head = blockIdx.x & 3, bt = blockIdx.x >> 2;
    const int b = bt / TT, t = bt % TT;
    const int tid = threadIdx.x, pr = tid >> 3, pc = (tid & 7) * 4;
    float acc[4] = {0.f, 0.f, 0.f, 0.f};

    for (int ci = 0; ci < 32; ++ci) {
        const float div  = __expf(-(float)(ci >> 1) * (logf(10000.0f) / 16.0f));
        const float ang  = (float)t * div;
        const float posv = (ci & 1) ? cosf(ang) : sinf(ang);
        const float* pl = v + ((size_t)bt * CC + head * DHH + ci) * NPIX;
        for (int idx = tid; idx < 34*34; idx += 256) {
            int r = idx / 34 - 1, c = idx % 34 - 1;
            splane[idx] = (r >= 0 && r < 32 && c >= 0 && c < 32) ? (pl[r*32 + c] + posv) : 0.f;
        }
        if (tid < 9) sw[tid] = attw[((head * 64) + 32 + ci) * 9 + tid];
        __syncthreads();
        float nb[3][6];
        #pragma unroll
        for (int r = 0; r < 3; ++r)
            #pragma unroll
            for (int c = 0; c < 6; ++c) nb[r][c] = splane[(pr + r) * 34 + pc + c];
        const float w0=sw[0],w1=sw[1],w2=sw[2],w3=sw[3],w4=sw[4],w5=sw[5],w6=sw[6],w7=sw[7],w8=sw[8];
        #pragma unroll
        for (int p = 0; p < 4; ++p) {
            float s = acc[p];
            s += w0*nb[0][p] + w1*nb[0][p+1] + w2*nb[0][p+2];
            s += w3*nb[1][p] + w4*nb[1][p+1] + w5*nb[1][p+2];
            s += w6*nb[2][p] + w7*nb[2][p+1] + w8*nb[2][p+2];
            acc[p] = s;
        }
        __syncthreads();
    }
    #pragma unroll
    for (int p = 0; p < 4; ++p)
        ak[(((size_t)(b * NHEAD + head) * TT) + t) * NPIX + pr * 32 + pc + p] = acc[p];
}

__global__ __launch_bounds__(256)
void softmax_ws_kernel(const float* __restrict__ ak, const float* __restrict__ v,
                       float* __restrict__ ws)
{
    const int chunk = blockIdx.x & 3;
    const int gid   = (blockIdx.x >> 2) * 256 + threadIdx.x;
    const int pix = gid & 1023, head = (gid >> 10) & 3, b = gid >> 12;
    float lg[TT], m = -1e30f;
    #pragma unroll
    for (int t = 0; t < TT; ++t) {
        lg[t] = ak[(((size_t)(b * NHEAD + head) * TT) + t) * NPIX + pix];
        m = fmaxf(m, lg[t]);
    }
    float s = 0.f;
    #pragma unroll
    for (int t = 0; t < TT; ++t) { lg[t] = expf(lg[t] - m); s += lg[t]; }
    const float inv = 1.f / s;
    const int c0 = chunk * 8;
    #pragma unroll
    for (int cc = 0; cc < 8; ++cc) {
        int c = c0 + cc;
        float a = 0.f;
        #pragma unroll
        for (int t = 0; t < TT; ++t)
            a += lg[t] * v[((size_t)(b * TT + t) * CC + head * DHH + c) * NPIX + pix];
        ws[((size_t)b * CC + head * DHH + c) * NPIX + pix] = a * inv;
    }
}

__global__ __launch_bounds__(256)
void groupnorm_kernel(const float* __restrict__ in, const float* __restrict__ gnw,
                      const float* __restrict__ gnb, float* __restrict__ out)
{
    __shared__ float rs[256], rs2[256];
    const int n = blockIdx.x >> 2, g = blockIdx.x & 3, tid = threadIdx.x;
    const float* p = in + (size_t)n * IMG + (size_t)g * 32 * NPIX;
    float s = 0.f, s2 = 0.f;
    for (int i = tid; i < 32 * NPIX; i += 256) { float x = p[i]; s += x; s2 += x * x; }
    rs[tid] = s; rs2[tid] = s2;
    __syncthreads();
    for (int off = 128; off > 0; off >>= 1) {
        if (tid < off) { rs[tid] += rs[tid + off]; rs2[tid] += rs2[tid + off]; }
        __syncthreads();
    }
    const float mean = rs[0] * (1.f / 32768.f);
    const float var  = rs2[0] * (1.f / 32768.f) - mean * mean;
    const float rstd = rsqrtf(var + 1e-5f);
    float* o = out + (size_t)n * IMG + (size_t)g * 32 * NPIX;
    for (int i = tid; i < 32 * NPIX; i += 256) {
        int c = g * 32 + (i >> 10);
        o[i] = (p[i] - mean) * rstd * gnw[c] + gnb[c];
    }
}

// ============================================================
extern "C" void kernel_launch(void* const* d_in, const int* in_sizes, int n_in,
                              void* d_out, int out_size)
{
    const float* x0   = (const float*)d_in[0];
    // q_w, q_b, att_b cancel exactly in the softmax
    const float* kvw  = (const float*)d_in[3];
    const float* kvb  = (const float*)d_in[4];
    const float* attw = (const float*)d_in[5];
    const float* ff1w = (const float*)d_in[7];
    const float* ff1b = (const float*)d_in[8];
    const float* ff2w = (const float*)d_in[9];
    const float* ff2b = (const float*)d_in[10];
    const float* gnw  = (const float*)d_in[11];
    const float* gnb  = (const float*)d_in[12];

    float *cur, *v, *ak, *ws, *att, *ff1, *ff2;
    __nv_bfloat16 *Y, *Wp;
    cudaGetSymbolAddress((void**)&cur, g_cur);
    cudaGetSymbolAddress((void**)&v,   g_v);
    cudaGetSymbolAddress((void**)&ak,  g_ak);
    cudaGetSymbolAddress((void**)&ws,  g_ws);
    cudaGetSymbolAddress((void**)&att, g_att);
    cudaGetSymbolAddress((void**)&ff1, g_ff1);
    cudaGetSymbolAddress((void**)&ff2, g_ff2);
    cudaGetSymbolAddress((void**)&Y,   g_Y);
    cudaGetSymbolAddress((void**)&Wp,  g_Wp);

    cudaFuncSetAttribute(conv_mma_kernel<true, false,false>, cudaFuncAttributeMaxDynamicSharedMemorySize, CSMEM);
    cudaFuncSetAttribute(conv_mma_kernel<false,true, false>, cudaFuncAttributeMaxDynamicSharedMemorySize, CSMEM);
    cudaFuncSetAttribute(conv_mma_kernel<false,false,true >, cudaFuncAttributeMaxDynamicSharedMemorySize, CSMEM);

    wprep_kernel<<<(WPTOT + 255) / 256, 256>>>(kvw, ff1w, ff2w, Wp);
    yzero_kernel<<<(YTOT / 2 + 255) / 256, 256>>>((unsigned*)Y);

    const float* lin = x0;
    for (int l = 0; l < 5; ++l) {
        prep_kernel<false><<<NT * 32, 256>>>(lin, nullptr, nullptr, Y);
        conv_mma_kernel<true,false,false><<<96, 512, CSMEM>>>(
            Y, Wp + (size_t)(l * 3 + 0) * WPERCONV, kvb + l * 128, nullptr, v);
        ak_kernel<<<NT * NHEAD, 256>>>(v, attw + (size_t)l * 4 * 64 * 9, ak);
        softmax_ws_kernel<<<128, 256>>>(ak, v, ws);
        prep_kernel<true><<<NT * 32, 256>>>(lin, ws, att, Y);
        conv_mma_kernel<false,true,false><<<96, 512, CSMEM>>>(
            Y, Wp + (size_t)(l * 3 + 1) * WPERCONV, ff1b + l * 128, nullptr, ff1);
        prep_kernel<false><<<NT * 32, 256>>>(ff1, nullptr, nullptr, Y);
        conv_mma_kernel<false,false,true><<<96, 512, CSMEM>>>(
            Y, Wp + (size_t)(l * 3 + 2) * WPERCONV, ff2b + l * 128, att, ff2);
        float* lout = (l == 4) ? (float*)d_out : cur;
        groupnorm_kernel<<<NT * 4, 256>>>(ff2, gnw + l * 128, gnb + l * 128, lout);
        lin = cur;
    }
}